// round 11
// baseline (speedup 1.0000x reference)
#include <cuda_runtime.h>
#include <cuda_fp16.h>
#include <math.h>
#include <stdint.h>

#define NXI 512
#define LDIM 128
#define NSTATES 128
#define NIN 64
#define HDIM 1152           // 2*NXI + LDIM
#define BATCHN 32768
#define EPSV 0.001f
#define ALPHA 0.55f
#define NEWTON_ITERS 7      // + fused first step = 8 squarings

// ---------------- device scratch ----------------
__device__ float g_H[HDIM * HDIM];
__device__ float g_H22[LDIM * LDIM];
__device__ float g_Zf[2][NXI * NXI];
__device__ float g_D11[LDIM * LDIM];
__device__ float g_LamInv[LDIM];
__device__ float g_pre[(size_t)BATCHN * LDIM];
__device__ unsigned g_barcnt, g_barep;     // software grid barrier state (zero-init)

// split-fp16 operand arrays
__device__ __half g_AH[(size_t)BATCHN * 768];   // [xi | eps | w]
__device__ __half g_AL[(size_t)BATCHN * 768];
__device__ __half g_WpreH[LDIM * 768];
__device__ __half g_WpreL[LDIM * 768];
__device__ __half g_WoutH[640 * 768];           // rows 576..639 stay zero
__device__ __half g_WoutL[640 * 768];
__device__ __half g_XtH[HDIM * HDIM];
__device__ __half g_XtL[HDIM * HDIM];
__device__ __half g_MH[NXI * NXI], g_ML[NXI * NXI];
__device__ __half g_ZH[2][NXI * NXI], g_ZL[2][NXI * NXI];
__device__ __half g_ZTH[2][NXI * NXI], g_ZTL[2][NXI * NXI];
__device__ __half g_TtH[NXI * NXI], g_TtL[NXI * NXI];
__device__ __half g_RtH[768 * NXI], g_RtL[768 * NXI];

// ---------------- PTX helpers ----------------
__device__ __forceinline__ uint32_t smem_u32(const void* p) {
    uint32_t a;
    asm("{ .reg .u64 t; cvta.to.shared.u64 t, %1; cvt.u32.u64 %0, t; }" : "=r"(a) : "l"(p));
    return a;
}
#define LDSM4(r0, r1, r2, r3, addr) \
    asm volatile("ldmatrix.sync.aligned.m8n8.x4.shared.b16 {%0,%1,%2,%3}, [%4];" \
                 : "=r"(r0), "=r"(r1), "=r"(r2), "=r"(r3) : "r"(addr))
#define MMA16816(d, a, b0, b1) \
    asm volatile("mma.sync.aligned.m16n8k16.row.col.f32.f16.f16.f32 " \
                 "{%0,%1,%2,%3},{%4,%5,%6,%7},{%8,%9},{%0,%1,%2,%3};" \
                 : "+f"(d[0]), "+f"(d[1]), "+f"(d[2]), "+f"(d[3]) \
                 : "r"(a[0]), "r"(a[1]), "r"(a[2]), "r"(a[3]), "r"(b0), "r"(b1))
#define CPA16(smaddr, gptr) \
    asm volatile("cp.async.cg.shared.global [%0], [%1], 16;" :: "r"(smaddr), "l"(gptr))
#define CPCOMMIT() asm volatile("cp.async.commit_group;" ::: "memory")
#define CPWAIT1()  asm volatile("cp.async.wait_group 1;" ::: "memory")
#define CPWAIT0()  asm volatile("cp.async.wait_group 0;" ::: "memory")

__device__ __forceinline__ void split_store(__half* H, __half* L, size_t idx, float v) {
    __half h = __float2half(v);
    H[idx] = h;
    L[idx] = __float2half(v - __half2float(h));
}

// software grid barrier (all NBLK CTAs co-resident). Replay-safe.
__device__ __forceinline__ void gridbar(int nblk) {
    __threadfence();
    __syncthreads();
    if (threadIdx.x == 0) {
        unsigned e = ((volatile unsigned*)&g_barep)[0];
        unsigned t = atomicAdd(&g_barcnt, 1);
        if (t == (unsigned)nblk - 1) {
            g_barcnt = 0;
            __threadfence();
            atomicAdd(&g_barep, 1);
        } else {
            while (((volatile unsigned*)&g_barep)[0] == e) {}
        }
    }
    __syncthreads();
    __threadfence();
}

// ============ big batch GEMM (128x128 tiles, cp.async 3-stage, 1 sync/chunk) ============
// 2-product fp16 split: hh + h_a*l_b (A-lo never touched).
// Ring indexing fixed: buffer(chunk) = chunk % 3 for BOTH read and prefetch.
#define BK 32
#define LDSW (BK + 8)
#define SA_AH 0u
#define SA_BH 10240u
#define SA_BL 20480u
#define SBUF  30720u
__global__ __launch_bounds__(256) void mma_gemm(
    const __half* __restrict__ Ah,
    const __half* __restrict__ Bh, const __half* __restrict__ Bl,
    int nchunks, int skip_at, int skip_amt, int lda, int ldb,
    float* __restrict__ out0, float* __restrict__ out1, int mode) {
    extern __shared__ char dsm[];
    const uint32_t smb = smem_u32(dsm);
    const int tid = threadIdx.x;
    const int wid = tid >> 5, lane = tid & 31;
    const size_t m0 = (size_t)blockIdx.y * 128;
    const int n0 = blockIdx.x * 128;
    const int wm = (wid & 3) * 32;
    const int wn = (wid >> 2) * 64;

    float acc[2][8][4] = {};
    const int lr = tid >> 1;
    const int lc = (tid & 1) * 16;
    const int am = wm + (lane & 15);
    const int ak = (lane >> 4) * 8;
    const int bn = wn + (lane & 7) + (lane >> 4) * 8;
    const int bk = ((lane >> 3) & 1) * 8;

    auto issue = [&](int c) {
        const int kc = c * BK;
        const int col = (kc >= skip_at) ? kc + skip_amt : kc;
        const size_t oa = (m0 + lr) * (size_t)lda + col + lc;
        const size_t ob = (size_t)(n0 + lr) * ldb + col + lc;
        const uint32_t so = smb + (uint32_t)(c % 3) * SBUF + (uint32_t)(lr * LDSW + lc) * 2;
        CPA16(so + SA_AH, Ah + oa); CPA16(so + SA_AH + 16, Ah + oa + 8);
        CPA16(so + SA_BH, Bh + ob); CPA16(so + SA_BH + 16, Bh + ob + 8);
        CPA16(so + SA_BL, Bl + ob); CPA16(so + SA_BL + 16, Bl + ob + 8);
        CPCOMMIT();
    };

    issue(0);
    if (nchunks > 1) issue(1);
    for (int c = 0; c < nchunks; ++c) {
        if (c + 1 < nchunks) { CPWAIT1(); } else { CPWAIT0(); }
        __syncthreads();
        if (c + 2 < nchunks) issue(c + 2);
        const uint32_t bb = smb + (uint32_t)(c % 3) * SBUF;
#pragma unroll
        for (int k16 = 0; k16 < BK; k16 += 16) {
            uint32_t ahf[2][4], bhf[4][4], blf[4][4];
#pragma unroll
            for (int mi = 0; mi < 2; ++mi) {
                const uint32_t off = bb + (uint32_t)(((am + mi * 16) * LDSW + ak + k16) * 2);
                LDSM4(ahf[mi][0], ahf[mi][1], ahf[mi][2], ahf[mi][3], off + SA_AH);
            }
#pragma unroll
            for (int j = 0; j < 4; ++j) {
                const uint32_t off = bb + (uint32_t)(((bn + j * 16) * LDSW + bk + k16) * 2);
                LDSM4(bhf[j][0], bhf[j][1], bhf[j][2], bhf[j][3], off + SA_BH);
                LDSM4(blf[j][0], blf[j][1], blf[j][2], blf[j][3], off + SA_BL);
            }
#pragma unroll
            for (int mi = 0; mi < 2; ++mi)
#pragma unroll
                for (int j = 0; j < 4; ++j)
#pragma unroll
                    for (int h = 0; h < 2; ++h) {
                        float* d = acc[mi][j * 2 + h];
                        MMA16816(d, ahf[mi], bhf[j][h * 2], bhf[j][h * 2 + 1]);
                        MMA16816(d, ahf[mi], blf[j][h * 2], blf[j][h * 2 + 1]);
                    }
        }
    }
    const int rrow = lane >> 2;
    const int rcol = (lane & 3) * 2;
#pragma unroll
    for (int mi = 0; mi < 2; ++mi)
#pragma unroll
        for (int j = 0; j < 8; ++j) {
            const float* d = acc[mi][j];
            const int n = n0 + wn + j * 8 + rcol;
#pragma unroll
            for (int half = 0; half < 2; ++half) {
                const size_t m = m0 + wm + mi * 16 + rrow + half * 8;
                const float v0 = d[half * 2 + 0], v1 = d[half * 2 + 1];
                if (mode == 0) {
                    *(float2*)(out0 + m * 128 + n) = make_float2(v0, v1);
                } else {
                    if (n < NIN) *(float2*)(out0 + m * NIN + n) = make_float2(v0, v1);
                    else if (n < 576) *(float2*)(out1 + m * NXI + (n - NIN)) = make_float2(v0, v1);
                }
            }
        }
}

// ============ 64x64 GEMM core (fp16 3-product) ============
#define LDS2 (BK + 8)
__device__ __forceinline__ void gemm64_core(
    const __half* __restrict__ Ah, const __half* __restrict__ Al,
    const __half* __restrict__ Bh, const __half* __restrict__ Bl,
    int K, int lda, int ldb, int m0, int n0,
    __half* sAh, __half* sAl, __half* sBh, __half* sBl,
    float acc[2][4][4]) {
    const int tid = threadIdx.x;
    const int wid = tid >> 5, lane = tid & 31;
    const int wm = (wid & 1) * 32;
    const int wn = (wid >> 1) * 32;
    const int lr = tid >> 1;
    const int lc = (tid & 1) * 16;
    const uint32_t uAh = smem_u32(sAh), uAl = smem_u32(sAl);
    const uint32_t uBh = smem_u32(sBh), uBl = smem_u32(sBl);
    const int am = wm + (lane & 15);
    const int ak = (lane >> 4) * 8;
    const int bn = wn + (lane & 7) + (lane >> 4) * 8;
    const int bk = ((lane >> 3) & 1) * 8;

#pragma unroll
    for (int mi = 0; mi < 2; ++mi)
#pragma unroll
        for (int j = 0; j < 4; ++j)
#pragma unroll
            for (int q = 0; q < 4; ++q) acc[mi][j][q] = 0.0f;

    uint4 pa[2][2], pb[2][2];
    auto gload = [&](int c) {
        const int col = c * BK;
        const size_t oa = (size_t)(m0 + lr) * lda + col + lc;
        const size_t ob = (size_t)(n0 + lr) * ldb + col + lc;
        pa[0][0] = *(const uint4*)(Ah + oa); pa[0][1] = *(const uint4*)(Ah + oa + 8);
        pa[1][0] = *(const uint4*)(Al + oa); pa[1][1] = *(const uint4*)(Al + oa + 8);
        pb[0][0] = *(const uint4*)(Bh + ob); pb[0][1] = *(const uint4*)(Bh + ob + 8);
        pb[1][0] = *(const uint4*)(Bl + ob); pb[1][1] = *(const uint4*)(Bl + ob + 8);
    };

    const int nchunks = K / BK;
    gload(0);
    for (int c = 0; c < nchunks; ++c) {
        const int so = lr * LDS2 + lc;
        *(uint4*)(sAh + so) = pa[0][0]; *(uint4*)(sAh + so + 8) = pa[0][1];
        *(uint4*)(sAl + so) = pa[1][0]; *(uint4*)(sAl + so + 8) = pa[1][1];
        *(uint4*)(sBh + so) = pb[0][0]; *(uint4*)(sBh + so + 8) = pb[0][1];
        *(uint4*)(sBl + so) = pb[1][0]; *(uint4*)(sBl + so + 8) = pb[1][1];
        __syncthreads();
        if (c + 1 < nchunks) gload(c + 1);
#pragma unroll
        for (int k16 = 0; k16 < BK; k16 += 16) {
            uint32_t ahf[2][4], alf[2][4], bhf[2][4], blf[2][4];
#pragma unroll
            for (int mi = 0; mi < 2; ++mi) {
                const uint32_t off = (uint32_t)(((am + mi * 16) * LDS2 + ak + k16) * 2);
                LDSM4(ahf[mi][0], ahf[mi][1], ahf[mi][2], ahf[mi][3], uAh + off);
                LDSM4(alf[mi][0], alf[mi][1], alf[mi][2], alf[mi][3], uAl + off);
            }
#pragma unroll
            for (int j = 0; j < 2; ++j) {
                const uint32_t off = (uint32_t)(((bn + j * 16) * LDS2 + bk + k16) * 2);
                LDSM4(bhf[j][0], bhf[j][1], bhf[j][2], bhf[j][3], uBh + off);
                LDSM4(blf[j][0], blf[j][1], blf[j][2], blf[j][3], uBl + off);
            }
#pragma unroll
            for (int mi = 0; mi < 2; ++mi)
#pragma unroll
                for (int j = 0; j < 2; ++j)
#pragma unroll
                    for (int h = 0; h < 2; ++h) {
                        float* d = acc[mi][j * 2 + h];
                        MMA16816(d, ahf[mi], bhf[j][h * 2], bhf[j][h * 2 + 1]);
                        MMA16816(d, ahf[mi], blf[j][h * 2], blf[j][h * 2 + 1]);
                        MMA16816(d, alf[mi], bhf[j][h * 2], bhf[j][h * 2 + 1]);
                    }
        }
        __syncthreads();
    }
}

// standalone small GEMM.
// emode 0 = fp32 out (+eps diag) ; 3 = splits out ; 4 = NEGATED splits out
__global__ __launch_bounds__(128) void tc2(
    const __half* __restrict__ Ah, const __half* __restrict__ Al,
    const __half* __restrict__ Bh, const __half* __restrict__ Bl,
    int K, int lda, int ldb,
    float* __restrict__ outf, int ldc,
    __half* __restrict__ oH, __half* __restrict__ oL, int emode) {
    __shared__ __half sAh[64 * LDS2], sAl[64 * LDS2];
    __shared__ __half sBh[64 * LDS2], sBl[64 * LDS2];
    const int tid = threadIdx.x;
    const int wid = tid >> 5, lane = tid & 31;
    const int m0 = blockIdx.y * 64;
    const int n0 = blockIdx.x * 64;
    const int wm = (wid & 1) * 32;
    const int wn = (wid >> 1) * 32;
    float acc[2][4][4];
    gemm64_core(Ah, Al, Bh, Bl, K, lda, ldb, m0, n0, sAh, sAl, sBh, sBl, acc);

    const int rrow = lane >> 2;
    const int rcol = (lane & 3) * 2;
#pragma unroll
    for (int mi = 0; mi < 2; ++mi)
#pragma unroll
        for (int j = 0; j < 4; ++j) {
            const float* d = acc[mi][j];
            const int n = n0 + wn + j * 8 + rcol;
#pragma unroll
            for (int half = 0; half < 2; ++half) {
                const int m = m0 + wm + mi * 16 + rrow + half * 8;
                float v0 = d[half * 2 + 0], v1 = d[half * 2 + 1];
                if (emode == 0) {
                    if (m == n) v0 += EPSV;
                    if (m == n + 1) v1 += EPSV;
                    *(float2*)(outf + (size_t)m * ldc + n) = make_float2(v0, v1);
                } else if (emode == 3) {
                    const size_t o = (size_t)m * ldc + n;
                    split_store(oH, oL, o, v0);
                    split_store(oH, oL, o + 1, v1);
                } else { // 4: negated splits
                    const size_t o = (size_t)m * ldc + n;
                    split_store(oH, oL, o, -v0);
                    split_store(oH, oL, o + 1, -v1);
                }
            }
        }
}

// ============ fused persistent Newton chain + Wout solve tail ============
#define NWT_BLOCKS 64
__global__ __launch_bounds__(128) void newton_fused() {
    __shared__ __half sAh[64 * LDS2], sAl[64 * LDS2];
    __shared__ __half sBh[64 * LDS2], sBl[64 * LDS2];
    const int tid = threadIdx.x;
    const int wid = tid >> 5, lane = tid & 31;
    const int m0 = (blockIdx.x >> 3) * 64;
    const int n0 = (blockIdx.x & 7) * 64;
    const int wm = (wid & 1) * 32;
    const int wn = (wid >> 1) * 32;
    const int rrow = lane >> 2;
    const int rcol = (lane & 3) * 2;
    float acc[2][4][4];

    int cur = 0;
    for (int it = 0; it < NEWTON_ITERS; ++it) {
        // phase 1: T = M * Z^T -> transposed splits Tt
        gemm64_core(g_MH, g_ML, g_ZTH[cur], g_ZTL[cur], NXI, NXI, NXI, m0, n0,
                    sAh, sAl, sBh, sBl, acc);
#pragma unroll
        for (int mi = 0; mi < 2; ++mi)
#pragma unroll
            for (int j = 0; j < 4; ++j) {
                const float* d = acc[mi][j];
                const int n = n0 + wn + j * 8 + rcol;
#pragma unroll
                for (int half = 0; half < 2; ++half) {
                    const int m = m0 + wm + mi * 16 + rrow + half * 8;
                    split_store(g_TtH, g_TtL, (size_t)n * NXI + m, d[half * 2 + 0]);
                    split_store(g_TtH, g_TtL, (size_t)(n + 1) * NXI + m, d[half * 2 + 1]);
                }
            }
        gridbar(NWT_BLOCKS);

        // phase 2: Zn = 2*Z - Z*T
        gemm64_core(g_ZH[cur], g_ZL[cur], g_TtH, g_TtL, NXI, NXI, NXI, m0, n0,
                    sAh, sAl, sBh, sBl, acc);
        const float* zin = g_Zf[cur];
        float* zout = g_Zf[cur ^ 1];
        const int nx = cur ^ 1;
#pragma unroll
        for (int mi = 0; mi < 2; ++mi)
#pragma unroll
            for (int j = 0; j < 4; ++j) {
                const float* d = acc[mi][j];
                const int n = n0 + wn + j * 8 + rcol;
#pragma unroll
                for (int half = 0; half < 2; ++half) {
                    const int m = m0 + wm + mi * 16 + rrow + half * 8;
                    const size_t o = (size_t)m * NXI + n;
                    float v0 = 2.0f * zin[o] - d[half * 2 + 0];
                    float v1 = 2.0f * zin[o + 1] - d[half * 2 + 1];
                    *(float2*)(zout + o) = make_float2(v0, v1);
                    split_store(g_ZH[nx], g_ZL[nx], o, v0);
                    split_store(g_ZH[nx], g_ZL[nx], o + 1, v1);
                    split_store(g_ZTH[nx], g_ZTL[nx], (size_t)n * NXI + m, v0);
                    split_store(g_ZTH[nx], g_ZTL[nx], (size_t)(n + 1) * NXI + m, v1);
                }
            }
        gridbar(NWT_BLOCKS);
        cur ^= 1;
    }

    // solve tail: Wout[64+m, n] = sum_k Z[m,k] * Rt[n,k]  (96 tiles over 64 CTAs)
    const int fin = NEWTON_ITERS & 1;
    for (int t = blockIdx.x; t < 96; t += NWT_BLOCKS) {
        const int sm0 = (t & 7) * 64;
        const int sn0 = (t >> 3) * 64;
        gemm64_core(g_ZH[fin], g_ZL[fin], g_RtH, g_RtL, NXI, NXI, NXI, sm0, sn0,
                    sAh, sAl, sBh, sBl, acc);
#pragma unroll
        for (int mi = 0; mi < 2; ++mi)
#pragma unroll
            for (int j = 0; j < 4; ++j) {
                const float* d = acc[mi][j];
                const int n = sn0 + wn + j * 8 + rcol;
#pragma unroll
                for (int half = 0; half < 2; ++half) {
                    const int m = sm0 + wm + mi * 16 + rrow + half * 8;
                    const size_t o = (size_t)(64 + m) * 768 + n;
                    split_store(g_WoutH, g_WoutL, o, d[half * 2 + 0]);
                    split_store(g_WoutH, g_WoutL, o + 1, d[half * 2 + 1]);
                }
            }
    }
}

// ---------------- builders ----------------
__global__ void conv_Xt(const float* __restrict__ X) {
    __shared__ float t[32][33];
    const int bx = blockIdx.x * 32, by = blockIdx.y * 32;
    const int tx = threadIdx.x, ty = threadIdx.y;
#pragma unroll
    for (int r = 0; r < 32; r += 8)
        t[ty + r][tx] = X[(size_t)(by + ty + r) * HDIM + bx + tx];
    __syncthreads();
#pragma unroll
    for (int r = 0; r < 32; r += 8) {
        const float v = t[tx][ty + r];
        split_store(g_XtH, g_XtL, (size_t)(bx + ty + r) * HDIM + by + tx, v);
    }
}
// M = D^-1 E (splits); Z1 = 2a*I - a^2*M ; dinv inline
__global__ void build_MZ(const float* __restrict__ Y) {
    int idx = blockIdx.x * blockDim.x + threadIdx.x;
    if (idx >= NXI * NXI) return;
    int i = idx >> 9, j = idx & 511;
    float dinv = 2.0f / (g_H[(size_t)i * HDIM + i] + g_H[(size_t)(640 + i) * HDIM + 640 + i]);
    float e = 0.5f * (g_H[(size_t)i * HDIM + j] + g_H[(size_t)(640 + i) * HDIM + 640 + j] +
                      Y[(size_t)i * NXI + j] - Y[(size_t)j * NXI + i]);
    float m = dinv * e;
    split_store(g_MH, g_ML, idx, m);
    float z = ((i == j) ? 2.0f * ALPHA : 0.0f) - ALPHA * ALPHA * m;
    g_Zf[0][idx] = z;
    split_store(g_ZH[0], g_ZL[0], idx, z);
    split_store(g_ZTH[0], g_ZTL[0], (size_t)j * NXI + i, z);
}
__global__ void build_Rt(const float* __restrict__ B2) {
    int idx = blockIdx.x * blockDim.x + threadIdx.x;
    if (idx >= NXI * 768) return;
    int i = idx / 768, c = idx - i * 768;
    float dinv = 2.0f / (g_H[(size_t)i * HDIM + i] + g_H[(size_t)(640 + i) * HDIM + 640 + i]);
    float v = (c < 640) ? g_H[(size_t)(640 + i) * HDIM + c] : B2[i * NSTATES + (c - 640)];
    split_store(g_RtH, g_RtL, (size_t)c * NXI + i, dinv * v);
}
__global__ void build_WoutTop(const float* __restrict__ C2, const float* __restrict__ D21,
                              const float* __restrict__ D22) {
    int idx = blockIdx.x * blockDim.x + threadIdx.x;
    if (idx >= NIN * 768) return;
    int rr = idx / 768, c = idx - rr * 768;
    float v = (c < NXI) ? C2[rr * NXI + c]
                        : (c < 640 ? D21[rr * LDIM + (c - NXI)] : D22[rr * NSTATES + (c - 640)]);
    split_store(g_WoutH, g_WoutL, idx, v);
}
// D12 columns of Wpre (no H dependency)
__global__ void build_WpreD12(const float* __restrict__ D12) {
    int idx = blockIdx.x * blockDim.x + threadIdx.x;
    if (idx >= LDIM * NSTATES) return;
    int rr = idx >> 7, c = idx & 127;
    split_store(g_WpreH, g_WpreL, (size_t)rr * 768 + 640 + c, D12[rr * NSTATES + c]);
}
// D11/LamInv from g_H22 (fp32, ld 128, eps already on diag)
__global__ void build_D11() {
    int idx = blockIdx.x * blockDim.x + threadIdx.x;
    if (idx >= LDIM * LDIM) return;
    int i = idx >> 7, j = idx & 127;
    g_D11[idx] = (j < i) ? -g_H22[i * 128 + j] : 0.0f;
    if (j == i) g_LamInv[i] = 2.0f / g_H22[i * 128 + i];
}
__global__ void conv_A(const float* __restrict__ xi, const float* __restrict__ w) {
    size_t idx = (size_t)blockIdx.x * blockDim.x + threadIdx.x;
    size_t b = idx / 160;
    int c0 = (int)(idx - b * 160) * 4;
    if (b >= BATCHN) return;
    float4 v;
    int dc;
    if (c0 < NXI) { v = *(const float4*)(xi + b * NXI + c0); dc = c0; }
    else          { v = *(const float4*)(w + b * NSTATES + (c0 - NXI)); dc = c0 + 128; }
    size_t o = b * 768 + dc;
    split_store(g_AH, g_AL, o + 0, v.x);
    split_store(g_AH, g_AL, o + 1, v.y);
    split_store(g_AH, g_AL, o + 2, v.z);
    split_store(g_AH, g_AL, o + 3, v.w);
}

// ---------------- tanh forward-substitution scan ----------------
__global__ __launch_bounds__(64) void eps_kernel() {
    __shared__ float es[128 * 64];
    __shared__ float li[128];
    int tid = threadIdx.x;
    size_t b = (size_t)blockIdx.x * 64 + tid;
    for (int i = tid; i < 128; i += 64) li[i] = g_LamInv[i];
    __syncthreads();
    for (int i = 0; i < 128; ++i) {
        float v = g_pre[b * 128 + i];
        const float* __restrict__ dr = &g_D11[i * 128];
        float v0 = 0.f, v1 = 0.f, v2 = 0.f, v3 = 0.f;
        int j = 0;
        for (; j + 3 < i; j += 4) {
            v0 = fmaf(es[(j + 0) * 64 + tid], dr[j + 0], v0);
            v1 = fmaf(es[(j + 1) * 64 + tid], dr[j + 1], v1);
            v2 = fmaf(es[(j + 2) * 64 + tid], dr[j + 2], v2);
            v3 = fmaf(es[(j + 3) * 64 + tid], dr[j + 3], v3);
        }
        for (; j < i; ++j) v0 = fmaf(es[j * 64 + tid], dr[j], v0);
        v += (v0 + v1) + (v2 + v3);
        es[i * 64 + tid] = tanhf(v * li[i]);
    }
    for (int i = 0; i < 128; ++i)
        split_store(g_AH, g_AL, b * 768 + 512 + i, es[i * 64 + tid]);
}

// ---------------- launch ----------------
extern "C" void kernel_launch(void* const* d_in, const int* in_sizes, int n_in,
                              void* d_out, int out_size) {
    (void)in_sizes; (void)n_in; (void)out_size;
    const float* w   = (const float*)d_in[1];
    const float* xi  = (const float*)d_in[2];
    const float* X   = (const float*)d_in[3];
    const float* Y   = (const float*)d_in[4];
    const float* B2  = (const float*)d_in[5];
    const float* C2  = (const float*)d_in[6];
    const float* D21 = (const float*)d_in[7];
    const float* D22 = (const float*)d_in[8];
    const float* D12 = (const float*)d_in[9];
    float* out   = (float*)d_out;
    float* out_u = out;
    float* out_x = out + (size_t)BATCHN * NIN;

    static cudaStream_t s2;
    static cudaEvent_t evStart, evA, evJoin;
    static bool inited = false;
    if (!inited) {
        cudaStreamCreateWithFlags(&s2, cudaStreamNonBlocking);
        cudaEventCreateWithFlags(&evStart, cudaEventDisableTiming);
        cudaEventCreateWithFlags(&evA, cudaEventDisableTiming);
        cudaEventCreateWithFlags(&evJoin, cudaEventDisableTiming);
        cudaFuncSetAttribute(mma_gemm, cudaFuncAttributeMaxDynamicSharedMemorySize, 3 * SBUF);
        inited = true;
    }

    float *pH, *pH22, *pPre;
    __half *pAH, *pWpreH, *pWpreL, *pWoutH, *pWoutL, *pXtH, *pXtL;
    cudaGetSymbolAddress((void**)&pH, g_H);
    cudaGetSymbolAddress((void**)&pH22, g_H22);
    cudaGetSymbolAddress((void**)&pPre, g_pre);
    cudaGetSymbolAddress((void**)&pAH, g_AH);
    cudaGetSymbolAddress((void**)&pWpreH, g_WpreH);
    cudaGetSymbolAddress((void**)&pWpreL, g_WpreL);
    cudaGetSymbolAddress((void**)&pWoutH, g_WoutH);
    cudaGetSymbolAddress((void**)&pWoutL, g_WoutL);
    cudaGetSymbolAddress((void**)&pXtH, g_XtH);
    cudaGetSymbolAddress((void**)&pXtL, g_XtL);

    // ---- top fork ----
    cudaEventRecord(evStart, 0);
    cudaStreamWaitEvent(s2, evStart, 0);
    conv_A<<<(BATCHN * 160 + 255) / 256, 256, 0, s2>>>(xi, w);
    build_WpreD12<<<(LDIM * NSTATES + 255) / 256, 256, 0, s2>>>(D12);

    // s0: Xt -> small slices needed by branch A, then record evA
    conv_Xt<<<dim3(HDIM / 32, HDIM / 32), dim3(32, 8)>>>(X);
    // Wpre = -H21 = -(Xt rows 512..639) @ (Xt rows 0..511)^T, negated splits
    tc2<<<dim3(8, 2), 128>>>(
        pXtH + 512 * HDIM, pXtL + 512 * HDIM, pXtH, pXtL, HDIM, HDIM, HDIM,
        nullptr, 768, pWpreH, pWpreL, 4);
    // H22 = (Xt rows 512..639) @ same^T + eps*I, fp32
    tc2<<<dim3(2, 2), 128>>>(
        pXtH + 512 * HDIM, pXtL + 512 * HDIM, pXtH + 512 * HDIM, pXtL + 512 * HDIM,
        HDIM, HDIM, HDIM, pH22, 128, nullptr, nullptr, 0);
    cudaEventRecord(evA, 0);
    cudaStreamWaitEvent(s2, evA, 0);

    // ---- branch A (s2): D11 -> pre-GEMM (2-product) -> eps ----
    build_D11<<<(LDIM * LDIM + 255) / 256, 256, 0, s2>>>();
    mma_gemm<<<dim3(1, BATCHN / 128), 256, 3 * SBUF, s2>>>(
        pAH, pWpreH, pWpreL, 20, 512, 128, 768, 768, pPre, nullptr, 0);
    eps_kernel<<<BATCHN / 64, 64, 0, s2>>>();
    cudaEventRecord(evJoin, s2);

    // ---- branch B (s0): full H -> builders -> fused Newton + solve ----
    tc2<<<dim3(HDIM / 64, HDIM / 64), 128>>>(
        pXtH, pXtL, pXtH, pXtL, HDIM, HDIM, HDIM,
        pH, HDIM, nullptr, nullptr, 0);
    build_MZ<<<(NXI * NXI + 255) / 256, 256>>>(Y);
    build_Rt<<<(NXI * 768 + 255) / 256, 256>>>(B2);
    build_WoutTop<<<(NIN * 768 + 255) / 256, 256>>>(C2, D21, D22);
    newton_fused<<<NWT_BLOCKS, 128>>>();

    // ---- join ----
    cudaStreamWaitEvent(0, evJoin, 0);

    // [u | xi_] = [xi|eps|w] @ Wout^T  (2-product fp16 split)
    mma_gemm<<<dim3(5, BATCHN / 128), 256, 3 * SBUF>>>(
        pAH, pWoutH, pWoutL, 24, 1 << 30, 0, 768, 768, out_u, out_x, 1);
}